// round 6
// baseline (speedup 1.0000x reference)
#include <cuda_runtime.h>
#include <cuda_bf16.h>
#include <cstdint>

#define BATCH 8
#define TLEN 256
#define DIM 256
#define NSTEP 12
#define NNEG 100
#define MROWS 2048
#define NCOLS 3072

__device__ float g_C[MROWS * NCOLS];                 // queries for all steps
__device__ __nv_bfloat16 g_tn[MROWS * DIM];          // normalized targets (bf16)
__device__ float g_part[NSTEP * MROWS];              // per-sample loss partials

// ---------------------------------------------------------------------------
// warp reductions (butterfly shfl — f32 redux does NOT exist on sm_103a)
// ---------------------------------------------------------------------------
__device__ __forceinline__ float wsum(float v) {
#pragma unroll
    for (int o = 16; o; o >>= 1) v += __shfl_xor_sync(0xffffffffu, v, o);
    return v;
}
__device__ __forceinline__ float wmax(float v) {
#pragma unroll
    for (int o = 16; o; o >>= 1) v = fmaxf(v, __shfl_xor_sync(0xffffffffu, v, o));
    return v;
}

// ---------------------------------------------------------------------------
// Threefry-2x32 (exact JAX rotation/key schedule)
// ---------------------------------------------------------------------------
__device__ __forceinline__ void tf2x32(uint32_t k0, uint32_t k1,
                                       uint32_t x0, uint32_t x1,
                                       uint32_t &o0, uint32_t &o1) {
    uint32_t ks2 = k0 ^ k1 ^ 0x1BD11BDAu;
    x0 += k0; x1 += k1;
#define TFR(r) { x0 += x1; x1 = __funnelshift_l(x1, x1, (r)); x1 ^= x0; }
    TFR(13) TFR(15) TFR(26) TFR(6)   x0 += k1;  x1 += ks2 + 1u;
    TFR(17) TFR(29) TFR(16) TFR(24)  x0 += ks2; x1 += k0 + 2u;
    TFR(13) TFR(15) TFR(26) TFR(6)   x0 += k0;  x1 += k1 + 3u;
    TFR(17) TFR(29) TFR(16) TFR(24)  x0 += k1;  x1 += ks2 + 4u;
    TFR(13) TFR(15) TFR(26) TFR(6)   x0 += ks2; x1 += k0 + 5u;
#undef TFR
    o0 = x0; o1 = x1;
}

__device__ __forceinline__ uint32_t tf_bits32(uint32_t k0, uint32_t k1, uint32_t i) {
    uint32_t a, b;
    tf2x32(k0, k1, 0u, i, a, b);
    return a ^ b;
}

// ---------------------------------------------------------------------------
// packed f32x2 helpers
// ---------------------------------------------------------------------------
__device__ __forceinline__ uint64_t pack_ff(float lo, float hi) {
    uint64_t r;
    asm("mov.b64 %0, {%1, %2};" : "=l"(r) : "f"(lo), "f"(hi));
    return r;
}
__device__ __forceinline__ uint64_t pack_uu(uint32_t lo, uint32_t hi) {
    uint64_t r;
    asm("mov.b64 %0, {%1, %2};" : "=l"(r) : "r"(lo), "r"(hi));
    return r;
}
__device__ __forceinline__ void fma2(uint64_t &acc, uint64_t a, uint64_t b) {
    asm("fma.rn.f32x2 %0, %1, %2, %3;" : "=l"(acc) : "l"(a), "l"(b), "l"(acc));
}
__device__ __forceinline__ uint64_t add2(uint64_t a, uint64_t b) {
    uint64_t r;
    asm("add.rn.f32x2 %0, %1, %2;" : "=l"(r) : "l"(a), "l"(b));
    return r;
}
__device__ __forceinline__ float hsum2(uint64_t v) {
    float lo, hi;
    asm("mov.b64 {%0, %1}, %2;" : "=f"(lo), "=f"(hi) : "l"(v));
    return lo + hi;
}

// bf16x2 word -> f32x2 pair. low elem exact (w<<16); high elem = raw word
// (junk low-16 mantissa bits, rel. perturbation <= 2^-8 ~ bf16 quant noise).
__device__ __forceinline__ uint64_t bf2_to_f32x2(uint32_t w) {
    return pack_uu(w << 16, w);
}

// ---------------------------------------------------------------------------
// Kernel 1: normalize target rows, store bf16
// ---------------------------------------------------------------------------
__global__ void k_norm_targets(const float* __restrict__ tgt) {
    int gw = (blockIdx.x * blockDim.x + threadIdx.x) >> 5;
    int lane = threadIdx.x & 31;
    if (gw >= BATCH * TLEN) return;
    const float4* r = reinterpret_cast<const float4*>(tgt + (size_t)gw * DIM);
    float4 a = r[lane * 2];
    float4 b = r[lane * 2 + 1];
    float ss = a.x*a.x + a.y*a.y + a.z*a.z + a.w*a.w
             + b.x*b.x + b.y*b.y + b.z*b.z + b.w*b.w;
    ss = wsum(ss);
    float inv = 1.0f / fmaxf(sqrtf(ss), 1e-12f);
    __nv_bfloat162 p0 = __floats2bfloat162_rn(a.x * inv, a.y * inv);
    __nv_bfloat162 p1 = __floats2bfloat162_rn(a.z * inv, a.w * inv);
    __nv_bfloat162 p2 = __floats2bfloat162_rn(b.x * inv, b.y * inv);
    __nv_bfloat162 p3 = __floats2bfloat162_rn(b.z * inv, b.w * inv);
    uint4 u;
    u.x = *reinterpret_cast<uint32_t*>(&p0);
    u.y = *reinterpret_cast<uint32_t*>(&p1);
    u.z = *reinterpret_cast<uint32_t*>(&p2);
    u.w = *reinterpret_cast<uint32_t*>(&p3);
    reinterpret_cast<uint4*>(g_tn + (size_t)gw * DIM)[lane] = u;
}

// ---------------------------------------------------------------------------
// Kernel 2: C[2048,3072] = A[2048,256] * Bw[3072,256]^T (12 step-GEMMs fused)
// ---------------------------------------------------------------------------
__global__ __launch_bounds__(256, 2) void k_gemm(const float* __restrict__ A,
                                                 const float* __restrict__ Bw) {
    __shared__ float As[8][132];
    __shared__ float Bs[8][132];
    int bm = blockIdx.y * 128;
    int bn = blockIdx.x * 128;
    int tid = threadIdx.x;
    int tx = tid & 15, ty = tid >> 4;
    int lr = tid >> 1;
    int lc = (tid & 1) * 4;
    const float* Ag = A + (size_t)(bm + lr) * DIM + lc;
    const float* Bg = Bw + (size_t)(bn + lr) * DIM + lc;
    float acc[8][8];
#pragma unroll
    for (int i = 0; i < 8; i++)
#pragma unroll
        for (int j = 0; j < 8; j++) acc[i][j] = 0.0f;

    for (int k0 = 0; k0 < DIM; k0 += 8) {
        float4 av = *reinterpret_cast<const float4*>(Ag + k0);
        float4 bv = *reinterpret_cast<const float4*>(Bg + k0);
        As[lc + 0][lr] = av.x; As[lc + 1][lr] = av.y;
        As[lc + 2][lr] = av.z; As[lc + 3][lr] = av.w;
        Bs[lc + 0][lr] = bv.x; Bs[lc + 1][lr] = bv.y;
        Bs[lc + 2][lr] = bv.z; Bs[lc + 3][lr] = bv.w;
        __syncthreads();
#pragma unroll
        for (int k = 0; k < 8; k++) {
            float ar[8], br[8];
            *reinterpret_cast<float4*>(&ar[0]) = *reinterpret_cast<const float4*>(&As[k][ty * 4]);
            *reinterpret_cast<float4*>(&ar[4]) = *reinterpret_cast<const float4*>(&As[k][64 + ty * 4]);
            *reinterpret_cast<float4*>(&br[0]) = *reinterpret_cast<const float4*>(&Bs[k][tx * 4]);
            *reinterpret_cast<float4*>(&br[4]) = *reinterpret_cast<const float4*>(&Bs[k][64 + tx * 4]);
#pragma unroll
            for (int i = 0; i < 8; i++)
#pragma unroll
                for (int j = 0; j < 8; j++) acc[i][j] = fmaf(ar[i], br[j], acc[i][j]);
        }
        __syncthreads();
    }
#pragma unroll
    for (int i = 0; i < 8; i++) {
        int m = bm + ((i < 4) ? (ty * 4 + i) : (64 + ty * 4 + i - 4));
        float* cp = g_C + (size_t)m * NCOLS + bn;
        *reinterpret_cast<float4*>(cp + tx * 4) =
            make_float4(acc[i][0], acc[i][1], acc[i][2], acc[i][3]);
        *reinterpret_cast<float4*>(cp + 64 + tx * 4) =
            make_float4(acc[i][4], acc[i][5], acc[i][6], acc[i][7]);
    }
}

// ---------------------------------------------------------------------------
// Kernel 3: add bias + L2-normalize each query row (warp per row)
// ---------------------------------------------------------------------------
__global__ void k_bias_norm(const float* __restrict__ bias) {
    int gw = (blockIdx.x * blockDim.x + threadIdx.x) >> 5;
    int lane = threadIdx.x & 31;
    if (gw >= MROWS * NSTEP) return;
    int m = gw / NSTEP, s = gw % NSTEP;
    float* row = g_C + (size_t)m * NCOLS + (size_t)s * DIM;
    const float4* b4 = reinterpret_cast<const float4*>(bias + (size_t)s * DIM);
    float4 v0 = reinterpret_cast<float4*>(row)[lane * 2];
    float4 v1 = reinterpret_cast<float4*>(row)[lane * 2 + 1];
    float4 c0 = b4[lane * 2];
    float4 c1 = b4[lane * 2 + 1];
    v0.x += c0.x; v0.y += c0.y; v0.z += c0.z; v0.w += c0.w;
    v1.x += c1.x; v1.y += c1.y; v1.z += c1.z; v1.w += c1.w;
    float ss = v0.x*v0.x + v0.y*v0.y + v0.z*v0.z + v0.w*v0.w
             + v1.x*v1.x + v1.y*v1.y + v1.z*v1.z + v1.w*v1.w;
    ss = wsum(ss);
    float inv = 1.0f / fmaxf(sqrtf(ss), 1e-12f);
    v0.x *= inv; v0.y *= inv; v0.z *= inv; v0.w *= inv;
    v1.x *= inv; v1.y *= inv; v1.z *= inv; v1.w *= inv;
    reinterpret_cast<float4*>(row)[lane * 2] = v0;
    reinterpret_cast<float4*>(row)[lane * 2 + 1] = v1;
}

// ---------------------------------------------------------------------------
// Kernel 4: per-(step,b,t) InfoNCE partial loss
//   8 warps; each warp computes 4 items concurrently (8 lanes per item).
//   All lanes stay CONVERGED: out-of-range slots clamp to item 100 and only
//   the final store is predicated (shfl_sync is always full-warp).
// ---------------------------------------------------------------------------
__global__ __launch_bounds__(256) void k_loss() {
    int s = blockIdx.y + 1;           // step 1..12
    int T2 = TLEN - s;
    int bt = blockIdx.x;              // 0..2047
    int b = bt >> 8, t = bt & 255;
    int tid = threadIdx.x;
    __shared__ float logits[101];
    __shared__ int sidx[101];         // row * 32 (uint4 units, 512B rows)
    if (t >= T2) {
        if (tid == 0) g_part[(size_t)(s - 1) * MROWS + bt] = 0.0f;
        return;
    }
    uint32_t span = (uint32_t)(BATCH * T2);
    if (tid < 101) {
        int row;
        if (tid == 0) {
            row = b * TLEN + t + s;   // positive
        } else {
            uint32_t k0, k1;
            tf2x32(0u, 1234u, 0u, (uint32_t)s, k0, k1);   // fold_in(key(1234), s)
            uint32_t n = span * NNEG;
            uint32_t i = (uint32_t)((b * T2 + t) * NNEG + (tid - 1));
            uint32_t hi = tf_bits32(k0, k1, i);
            uint32_t lo = tf_bits32(k0, k1, n + i);
            uint32_t m16 = 65536u % span;
            uint32_t mult = (m16 * m16) % span;
            uint32_t off = ((hi % span) * mult + (lo % span)) % span;
            uint32_t b2 = off / (uint32_t)T2;
            uint32_t t2 = off - b2 * (uint32_t)T2;
            row = (int)(b2 * TLEN + (uint32_t)s + t2);
        }
        sidx[tid] = row * 32;
    }
    __syncthreads();

    int lane = tid & 31, w = tid >> 5;
    int sub = lane & 7;               // lane within item
    int grp = lane >> 3;              // item slot within warp (0..3)

    // Pre-stage query pairs for this lane's 4 word slots (u = i*8 + sub);
    // uint4 slot u covers f32 elements [u*8, u*8+8).
    const float* qrow = g_C + (size_t)(b * TLEN + t) * NCOLS + (size_t)(s - 1) * DIM;
    const float4* q4 = reinterpret_cast<const float4*>(qrow);
    uint64_t qp[4][4];
#pragma unroll
    for (int i = 0; i < 4; i++) {
        int u = i * 8 + sub;
        float4 qa = q4[u * 2];
        float4 qb = q4[u * 2 + 1];
        qp[i][0] = pack_ff(qa.x, qa.y);
        qp[i][1] = pack_ff(qa.z, qa.w);
        qp[i][2] = pack_ff(qb.x, qb.y);
        qp[i][3] = pack_ff(qb.z, qb.w);
    }

    const uint4* tn4 = reinterpret_cast<const uint4*>(g_tn);
#pragma unroll
    for (int it = 0; it < 4; it++) {
        int g = it * 32 + (w << 2) + grp;
        int gc = min(g, 100);          // clamp: keeps all 32 lanes converged
        int base = sidx[gc];
        uint64_t a0 = 0, a1 = 0;
#pragma unroll
        for (int i = 0; i < 4; i++) {
            uint4 v = __ldg(tn4 + base + i * 8 + sub);
            fma2(a0, bf2_to_f32x2(v.x), qp[i][0]);
            fma2(a1, bf2_to_f32x2(v.y), qp[i][1]);
            fma2(a0, bf2_to_f32x2(v.z), qp[i][2]);
            fma2(a1, bf2_to_f32x2(v.w), qp[i][3]);
        }
        float dot = hsum2(add2(a0, a1));
        dot += __shfl_xor_sync(0xffffffffu, dot, 4);
        dot += __shfl_xor_sync(0xffffffffu, dot, 2);
        dot += __shfl_xor_sync(0xffffffffu, dot, 1);
        if (g < 101 && sub == 0) logits[g] = dot * 10.0f;   // /TEMP
    }
    __syncthreads();

    if (w == 0) {
        float mx = -1e30f;
        for (int i = lane; i < 101; i += 32) mx = fmaxf(mx, logits[i]);
        mx = wmax(mx);
        float sum = 0.0f;
        for (int i = lane; i < 101; i += 32) sum += __expf(logits[i] - mx);
        sum = wsum(sum);
        if (lane == 0) {
            float lse = mx + __logf(sum);
            g_part[(size_t)(s - 1) * MROWS + bt] =
                (lse - logits[0]) / (float)(NSTEP * BATCH * T2);
        }
    }
}

// ---------------------------------------------------------------------------
// Kernel 5: deterministic final reduction
// ---------------------------------------------------------------------------
__global__ void k_reduce(float* __restrict__ out) {
    __shared__ float sm[256];
    int tid = threadIdx.x;
    float s = 0.0f;
    for (int i = tid; i < NSTEP * MROWS; i += 256) s += g_part[i];
    sm[tid] = s;
    __syncthreads();
    for (int o = 128; o; o >>= 1) {
        if (tid < o) sm[tid] += sm[tid + o];
        __syncthreads();
    }
    if (tid == 0) out[0] = sm[0];
}

// ---------------------------------------------------------------------------
extern "C" void kernel_launch(void* const* d_in, const int* in_sizes, int n_in,
                              void* d_out, int out_size) {
    const float* ctx  = (const float*)d_in[0];
    const float* tgt  = (const float*)d_in[1];
    const float* W    = (const float*)d_in[2];
    const float* bias = (const float*)d_in[3];
    float* out = (float*)d_out;

    k_norm_targets<<<(BATCH * TLEN) / 8, 256>>>(tgt);
    k_gemm<<<dim3(NCOLS / 128, MROWS / 128), 256>>>(ctx, W);
    k_bias_norm<<<(MROWS * NSTEP) / 8, 256>>>(bias);
    k_loss<<<dim3(MROWS, NSTEP), 256>>>();
    k_reduce<<<1, 256>>>(out);
}

// round 8
// speedup vs baseline: 1.1173x; 1.1173x over previous
#include <cuda_runtime.h>
#include <cuda_bf16.h>
#include <cstdint>

#define BATCH 8
#define TLEN 256
#define DIM 256
#define NSTEP 12
#define NNEG 100
#define MROWS 2048
#define NCOLS 3072

__device__ float g_C[MROWS * NCOLS];                 // queries for all steps
__device__ __nv_bfloat16 g_tn[MROWS * DIM];          // normalized targets (bf16)
__device__ float g_part[NSTEP * MROWS];              // per-sample loss partials

// ---------------------------------------------------------------------------
// warp reductions (butterfly shfl — f32 redux does NOT exist on sm_103a)
// ---------------------------------------------------------------------------
__device__ __forceinline__ float wsum(float v) {
#pragma unroll
    for (int o = 16; o; o >>= 1) v += __shfl_xor_sync(0xffffffffu, v, o);
    return v;
}
__device__ __forceinline__ float wmax(float v) {
#pragma unroll
    for (int o = 16; o; o >>= 1) v = fmaxf(v, __shfl_xor_sync(0xffffffffu, v, o));
    return v;
}

// ---------------------------------------------------------------------------
// Threefry-2x32 (exact JAX rotation/key schedule)
// ---------------------------------------------------------------------------
__device__ __forceinline__ void tf2x32(uint32_t k0, uint32_t k1,
                                       uint32_t x0, uint32_t x1,
                                       uint32_t &o0, uint32_t &o1) {
    uint32_t ks2 = k0 ^ k1 ^ 0x1BD11BDAu;
    x0 += k0; x1 += k1;
#define TFR(r) { x0 += x1; x1 = __funnelshift_l(x1, x1, (r)); x1 ^= x0; }
    TFR(13) TFR(15) TFR(26) TFR(6)   x0 += k1;  x1 += ks2 + 1u;
    TFR(17) TFR(29) TFR(16) TFR(24)  x0 += ks2; x1 += k0 + 2u;
    TFR(13) TFR(15) TFR(26) TFR(6)   x0 += k0;  x1 += k1 + 3u;
    TFR(17) TFR(29) TFR(16) TFR(24)  x0 += k1;  x1 += ks2 + 4u;
    TFR(13) TFR(15) TFR(26) TFR(6)   x0 += ks2; x1 += k0 + 5u;
#undef TFR
    o0 = x0; o1 = x1;
}

__device__ __forceinline__ uint32_t tf_bits32(uint32_t k0, uint32_t k1, uint32_t i) {
    uint32_t a, b;
    tf2x32(k0, k1, 0u, i, a, b);
    return a ^ b;
}

// ---------------------------------------------------------------------------
// packed f32x2 helpers
// ---------------------------------------------------------------------------
__device__ __forceinline__ uint64_t pack_ff(float lo, float hi) {
    uint64_t r;
    asm("mov.b64 %0, {%1, %2};" : "=l"(r) : "f"(lo), "f"(hi));
    return r;
}
__device__ __forceinline__ uint64_t pack_uu(uint32_t lo, uint32_t hi) {
    uint64_t r;
    asm("mov.b64 %0, {%1, %2};" : "=l"(r) : "r"(lo), "r"(hi));
    return r;
}
__device__ __forceinline__ void fma2(uint64_t &acc, uint64_t a, uint64_t b) {
    asm("fma.rn.f32x2 %0, %1, %2, %3;" : "=l"(acc) : "l"(a), "l"(b), "l"(acc));
}
__device__ __forceinline__ uint64_t add2(uint64_t a, uint64_t b) {
    uint64_t r;
    asm("add.rn.f32x2 %0, %1, %2;" : "=l"(r) : "l"(a), "l"(b));
    return r;
}
__device__ __forceinline__ float hsum2(uint64_t v) {
    float lo, hi;
    asm("mov.b64 {%0, %1}, %2;" : "=f"(lo), "=f"(hi) : "l"(v));
    return lo + hi;
}

// bf16x2 word -> f32x2 pair. low elem exact (w<<16); high elem = raw word
// (junk low-16 mantissa bits, rel. perturbation <= 2^-8 ~ bf16 quant noise).
__device__ __forceinline__ uint64_t bf2_to_f32x2(uint32_t w) {
    return pack_uu(w << 16, w);
}

// ---------------------------------------------------------------------------
// Kernel 1: normalize target rows, store bf16
// ---------------------------------------------------------------------------
__global__ void k_norm_targets(const float* __restrict__ tgt) {
    int gw = (blockIdx.x * blockDim.x + threadIdx.x) >> 5;
    int lane = threadIdx.x & 31;
    if (gw >= BATCH * TLEN) return;
    const float4* r = reinterpret_cast<const float4*>(tgt + (size_t)gw * DIM);
    float4 a = r[lane * 2];
    float4 b = r[lane * 2 + 1];
    float ss = a.x*a.x + a.y*a.y + a.z*a.z + a.w*a.w
             + b.x*b.x + b.y*b.y + b.z*b.z + b.w*b.w;
    ss = wsum(ss);
    float inv = 1.0f / fmaxf(sqrtf(ss), 1e-12f);
    __nv_bfloat162 p0 = __floats2bfloat162_rn(a.x * inv, a.y * inv);
    __nv_bfloat162 p1 = __floats2bfloat162_rn(a.z * inv, a.w * inv);
    __nv_bfloat162 p2 = __floats2bfloat162_rn(b.x * inv, b.y * inv);
    __nv_bfloat162 p3 = __floats2bfloat162_rn(b.z * inv, b.w * inv);
    uint4 u;
    u.x = *reinterpret_cast<uint32_t*>(&p0);
    u.y = *reinterpret_cast<uint32_t*>(&p1);
    u.z = *reinterpret_cast<uint32_t*>(&p2);
    u.w = *reinterpret_cast<uint32_t*>(&p3);
    reinterpret_cast<uint4*>(g_tn + (size_t)gw * DIM)[lane] = u;
}

// ---------------------------------------------------------------------------
// Kernel 2: C[2048,3072] = A[2048,256] * Bw[3072,256]^T (12 step-GEMMs fused)
// ---------------------------------------------------------------------------
__global__ __launch_bounds__(256, 2) void k_gemm(const float* __restrict__ A,
                                                 const float* __restrict__ Bw) {
    __shared__ float As[8][132];
    __shared__ float Bs[8][132];
    int bm = blockIdx.y * 128;
    int bn = blockIdx.x * 128;
    int tid = threadIdx.x;
    int tx = tid & 15, ty = tid >> 4;
    int lr = tid >> 1;
    int lc = (tid & 1) * 4;
    const float* Ag = A + (size_t)(bm + lr) * DIM + lc;
    const float* Bg = Bw + (size_t)(bn + lr) * DIM + lc;
    float acc[8][8];
#pragma unroll
    for (int i = 0; i < 8; i++)
#pragma unroll
        for (int j = 0; j < 8; j++) acc[i][j] = 0.0f;

    for (int k0 = 0; k0 < DIM; k0 += 8) {
        float4 av = *reinterpret_cast<const float4*>(Ag + k0);
        float4 bv = *reinterpret_cast<const float4*>(Bg + k0);
        As[lc + 0][lr] = av.x; As[lc + 1][lr] = av.y;
        As[lc + 2][lr] = av.z; As[lc + 3][lr] = av.w;
        Bs[lc + 0][lr] = bv.x; Bs[lc + 1][lr] = bv.y;
        Bs[lc + 2][lr] = bv.z; Bs[lc + 3][lr] = bv.w;
        __syncthreads();
#pragma unroll
        for (int k = 0; k < 8; k++) {
            float ar[8], br[8];
            *reinterpret_cast<float4*>(&ar[0]) = *reinterpret_cast<const float4*>(&As[k][ty * 4]);
            *reinterpret_cast<float4*>(&ar[4]) = *reinterpret_cast<const float4*>(&As[k][64 + ty * 4]);
            *reinterpret_cast<float4*>(&br[0]) = *reinterpret_cast<const float4*>(&Bs[k][tx * 4]);
            *reinterpret_cast<float4*>(&br[4]) = *reinterpret_cast<const float4*>(&Bs[k][64 + tx * 4]);
#pragma unroll
            for (int i = 0; i < 8; i++)
#pragma unroll
                for (int j = 0; j < 8; j++) acc[i][j] = fmaf(ar[i], br[j], acc[i][j]);
        }
        __syncthreads();
    }
#pragma unroll
    for (int i = 0; i < 8; i++) {
        int m = bm + ((i < 4) ? (ty * 4 + i) : (64 + ty * 4 + i - 4));
        float* cp = g_C + (size_t)m * NCOLS + bn;
        *reinterpret_cast<float4*>(cp + tx * 4) =
            make_float4(acc[i][0], acc[i][1], acc[i][2], acc[i][3]);
        *reinterpret_cast<float4*>(cp + 64 + tx * 4) =
            make_float4(acc[i][4], acc[i][5], acc[i][6], acc[i][7]);
    }
}

// ---------------------------------------------------------------------------
// Kernel 3: add bias + L2-normalize each query row (warp per row)
// ---------------------------------------------------------------------------
__global__ void k_bias_norm(const float* __restrict__ bias) {
    int gw = (blockIdx.x * blockDim.x + threadIdx.x) >> 5;
    int lane = threadIdx.x & 31;
    if (gw >= MROWS * NSTEP) return;
    int m = gw / NSTEP, s = gw % NSTEP;
    float* row = g_C + (size_t)m * NCOLS + (size_t)s * DIM;
    const float4* b4 = reinterpret_cast<const float4*>(bias + (size_t)s * DIM);
    float4 v0 = reinterpret_cast<float4*>(row)[lane * 2];
    float4 v1 = reinterpret_cast<float4*>(row)[lane * 2 + 1];
    float4 c0 = b4[lane * 2];
    float4 c1 = b4[lane * 2 + 1];
    v0.x += c0.x; v0.y += c0.y; v0.z += c0.z; v0.w += c0.w;
    v1.x += c1.x; v1.y += c1.y; v1.z += c1.z; v1.w += c1.w;
    float ss = v0.x*v0.x + v0.y*v0.y + v0.z*v0.z + v0.w*v0.w
             + v1.x*v1.x + v1.y*v1.y + v1.z*v1.z + v1.w*v1.w;
    ss = wsum(ss);
    float inv = 1.0f / fmaxf(sqrtf(ss), 1e-12f);
    v0.x *= inv; v0.y *= inv; v0.z *= inv; v0.w *= inv;
    v1.x *= inv; v1.y *= inv; v1.z *= inv; v1.w *= inv;
    reinterpret_cast<float4*>(row)[lane * 2] = v0;
    reinterpret_cast<float4*>(row)[lane * 2 + 1] = v1;
}

// ---------------------------------------------------------------------------
// Kernel 4: per-(step,b,t) InfoNCE partial loss
//   Warp-per-item (13 items/warp), per-lane partials go to smem (no shfl
//   chains); one 101-thread pass reduces 32 lane-partials per item.
//   Low register pressure -> high occupancy; all warp ops fully converged.
// ---------------------------------------------------------------------------
__global__ __launch_bounds__(256) void k_loss() {
    int s = blockIdx.y + 1;           // step 1..12
    int T2 = TLEN - s;
    int bt = blockIdx.x;              // 0..2047
    int b = bt >> 8, t = bt & 255;
    int tid = threadIdx.x;
    __shared__ float sp[101 * 33];    // per-lane partials, stride 33 (pad)
    __shared__ float logits[101];
    __shared__ int sidx[101];         // row * 32 (uint4 units, 512B rows)
    if (t >= T2) {
        if (tid == 0) g_part[(size_t)(s - 1) * MROWS + bt] = 0.0f;
        return;
    }
    uint32_t span = (uint32_t)(BATCH * T2);
    if (tid < 101) {
        int row;
        if (tid == 0) {
            row = b * TLEN + t + s;   // positive
        } else {
            uint32_t k0, k1;
            tf2x32(0u, 1234u, 0u, (uint32_t)s, k0, k1);   // fold_in(key(1234), s)
            uint32_t n = span * NNEG;
            uint32_t i = (uint32_t)((b * T2 + t) * NNEG + (tid - 1));
            uint32_t hi = tf_bits32(k0, k1, i);
            uint32_t lo = tf_bits32(k0, k1, n + i);
            uint32_t m16 = 65536u % span;
            uint32_t mult = (m16 * m16) % span;
            uint32_t off = ((hi % span) * mult + (lo % span)) % span;
            uint32_t b2 = off / (uint32_t)T2;
            uint32_t t2 = off - b2 * (uint32_t)T2;
            row = (int)(b2 * TLEN + (uint32_t)s + t2);
        }
        sidx[tid] = row * 32;
    }
    __syncthreads();

    int lane = tid & 31, w = tid >> 5;

    // Query: this lane's 8 contiguous f32 (one uint4 slot of the row) as 4 pairs
    const float* qrow = g_C + (size_t)(b * TLEN + t) * NCOLS + (size_t)(s - 1) * DIM;
    const float4* q4 = reinterpret_cast<const float4*>(qrow);
    float4 qa = q4[lane * 2];
    float4 qb = q4[lane * 2 + 1];
    uint64_t qv0 = pack_ff(qa.x, qa.y);
    uint64_t qv1 = pack_ff(qa.z, qa.w);
    uint64_t qv2 = pack_ff(qb.x, qb.y);
    uint64_t qv3 = pack_ff(qb.z, qb.w);

    const uint4* tn4 = reinterpret_cast<const uint4*>(g_tn);
#pragma unroll 4
    for (int it = 0; it < 13; it++) {
        int g = it * 8 + w;           // item id; uniform across warp
        int gc = min(g, 100);
        uint4 v = __ldg(tn4 + sidx[gc] + lane);
        uint64_t a0 = 0, a1 = 0;
        fma2(a0, bf2_to_f32x2(v.x), qv0);
        fma2(a1, bf2_to_f32x2(v.y), qv1);
        fma2(a0, bf2_to_f32x2(v.z), qv2);
        fma2(a1, bf2_to_f32x2(v.w), qv3);
        float part = hsum2(add2(a0, a1));
        if (g < 101) sp[gc * 33 + lane] = part;   // warp-uniform predicate
    }
    __syncthreads();

    // Reduce 32 lane-partials per item (thread i -> item i; banks (i+k)%32,
    // conflict-free at every k thanks to the stride-33 padding)
    if (tid < 101) {
        const float* r = sp + tid * 33;
        float s0 = 0.f, s1 = 0.f, s2 = 0.f, s3 = 0.f;
#pragma unroll
        for (int k = 0; k < 32; k += 4) {
            s0 += r[k]; s1 += r[k + 1]; s2 += r[k + 2]; s3 += r[k + 3];
        }
        logits[tid] = ((s0 + s1) + (s2 + s3)) * 10.0f;   // /TEMP
    }
    __syncthreads();

    if (w == 0) {
        float mx = -1e30f;
        for (int i = lane; i < 101; i += 32) mx = fmaxf(mx, logits[i]);
        mx = wmax(mx);
        float sum = 0.0f;
        for (int i = lane; i < 101; i += 32) sum += __expf(logits[i] - mx);
        sum = wsum(sum);
        if (lane == 0) {
            float lse = mx + __logf(sum);
            g_part[(size_t)(s - 1) * MROWS + bt] =
                (lse - logits[0]) / (float)(NSTEP * BATCH * T2);
        }
    }
}

// ---------------------------------------------------------------------------
// Kernel 5: deterministic final reduction
// ---------------------------------------------------------------------------
__global__ void k_reduce(float* __restrict__ out) {
    __shared__ float sm[256];
    int tid = threadIdx.x;
    float s = 0.0f;
    for (int i = tid; i < NSTEP * MROWS; i += 256) s += g_part[i];
    sm[tid] = s;
    __syncthreads();
    for (int o = 128; o; o >>= 1) {
        if (tid < o) sm[tid] += sm[tid + o];
        __syncthreads();
    }
    if (tid == 0) out[0] = sm[0];
}

// ---------------------------------------------------------------------------
extern "C" void kernel_launch(void* const* d_in, const int* in_sizes, int n_in,
                              void* d_out, int out_size) {
    const float* ctx  = (const float*)d_in[0];
    const float* tgt  = (const float*)d_in[1];
    const float* W    = (const float*)d_in[2];
    const float* bias = (const float*)d_in[3];
    float* out = (float*)d_out;

    k_norm_targets<<<(BATCH * TLEN) / 8, 256>>>(tgt);
    k_gemm<<<dim3(NCOLS / 128, MROWS / 128), 256>>>(ctx, W);
    k_bias_norm<<<(MROWS * NSTEP) / 8, 256>>>(bias);
    k_loss<<<dim3(MROWS, NSTEP), 256>>>();
    k_reduce<<<1, 256>>>(out);
}

// round 9
// speedup vs baseline: 1.1646x; 1.0423x over previous
#include <cuda_runtime.h>
#include <cuda_bf16.h>
#include <cstdint>

#define BATCH 8
#define TLEN 256
#define DIM 256
#define NSTEP 12
#define NNEG 100
#define MROWS 2048
#define NCOLS 3072

__device__ float g_C[MROWS * NCOLS];                 // queries for all steps
__device__ __nv_bfloat16 g_tn[MROWS * DIM];          // normalized targets (bf16)
__device__ float g_part[NSTEP * MROWS];              // per-sample loss partials

// ---------------------------------------------------------------------------
// warp reductions (butterfly shfl — f32 redux does NOT exist on sm_103a)
// ---------------------------------------------------------------------------
__device__ __forceinline__ float wsum(float v) {
#pragma unroll
    for (int o = 16; o; o >>= 1) v += __shfl_xor_sync(0xffffffffu, v, o);
    return v;
}
__device__ __forceinline__ float wmax(float v) {
#pragma unroll
    for (int o = 16; o; o >>= 1) v = fmaxf(v, __shfl_xor_sync(0xffffffffu, v, o));
    return v;
}

// ---------------------------------------------------------------------------
// Threefry-2x32 (exact JAX rotation/key schedule)
// ---------------------------------------------------------------------------
__device__ __forceinline__ void tf2x32(uint32_t k0, uint32_t k1,
                                       uint32_t x0, uint32_t x1,
                                       uint32_t &o0, uint32_t &o1) {
    uint32_t ks2 = k0 ^ k1 ^ 0x1BD11BDAu;
    x0 += k0; x1 += k1;
#define TFR(r) { x0 += x1; x1 = __funnelshift_l(x1, x1, (r)); x1 ^= x0; }
    TFR(13) TFR(15) TFR(26) TFR(6)   x0 += k1;  x1 += ks2 + 1u;
    TFR(17) TFR(29) TFR(16) TFR(24)  x0 += ks2; x1 += k0 + 2u;
    TFR(13) TFR(15) TFR(26) TFR(6)   x0 += k0;  x1 += k1 + 3u;
    TFR(17) TFR(29) TFR(16) TFR(24)  x0 += k1;  x1 += ks2 + 4u;
    TFR(13) TFR(15) TFR(26) TFR(6)   x0 += ks2; x1 += k0 + 5u;
#undef TFR
    o0 = x0; o1 = x1;
}

__device__ __forceinline__ uint32_t tf_bits32(uint32_t k0, uint32_t k1, uint32_t i) {
    uint32_t a, b;
    tf2x32(k0, k1, 0u, i, a, b);
    return a ^ b;
}

// ---------------------------------------------------------------------------
// bf16x2 fused multiply-add (elementwise, bf16 accumulate)
// ---------------------------------------------------------------------------
__device__ __forceinline__ void bfma2(uint32_t &acc, uint32_t a, uint32_t b) {
    asm("fma.rn.bf16x2 %0, %1, %2, %3;" : "=r"(acc) : "r"(a), "r"(b), "r"(acc));
}
__device__ __forceinline__ uint32_t f2_to_bf2(float lo, float hi) {
    __nv_bfloat162 p = __floats2bfloat162_rn(lo, hi);   // .x = lo (low half)
    return *reinterpret_cast<uint32_t*>(&p);
}

// ---------------------------------------------------------------------------
// Kernel 1: normalize target rows, store bf16
// ---------------------------------------------------------------------------
__global__ void k_norm_targets(const float* __restrict__ tgt) {
    int gw = (blockIdx.x * blockDim.x + threadIdx.x) >> 5;
    int lane = threadIdx.x & 31;
    if (gw >= BATCH * TLEN) return;
    const float4* r = reinterpret_cast<const float4*>(tgt + (size_t)gw * DIM);
    float4 a = r[lane * 2];
    float4 b = r[lane * 2 + 1];
    float ss = a.x*a.x + a.y*a.y + a.z*a.z + a.w*a.w
             + b.x*b.x + b.y*b.y + b.z*b.z + b.w*b.w;
    ss = wsum(ss);
    float inv = 1.0f / fmaxf(sqrtf(ss), 1e-12f);
    uint4 u;
    u.x = f2_to_bf2(a.x * inv, a.y * inv);
    u.y = f2_to_bf2(a.z * inv, a.w * inv);
    u.z = f2_to_bf2(b.x * inv, b.y * inv);
    u.w = f2_to_bf2(b.z * inv, b.w * inv);
    reinterpret_cast<uint4*>(g_tn + (size_t)gw * DIM)[lane] = u;
}

// ---------------------------------------------------------------------------
// Kernel 2: C[2048,3072] = A[2048,256] * Bw[3072,256]^T (12 step-GEMMs fused)
// ---------------------------------------------------------------------------
__global__ __launch_bounds__(256, 2) void k_gemm(const float* __restrict__ A,
                                                 const float* __restrict__ Bw) {
    __shared__ float As[8][132];
    __shared__ float Bs[8][132];
    int bm = blockIdx.y * 128;
    int bn = blockIdx.x * 128;
    int tid = threadIdx.x;
    int tx = tid & 15, ty = tid >> 4;
    int lr = tid >> 1;
    int lc = (tid & 1) * 4;
    const float* Ag = A + (size_t)(bm + lr) * DIM + lc;
    const float* Bg = Bw + (size_t)(bn + lr) * DIM + lc;
    float acc[8][8];
#pragma unroll
    for (int i = 0; i < 8; i++)
#pragma unroll
        for (int j = 0; j < 8; j++) acc[i][j] = 0.0f;

    for (int k0 = 0; k0 < DIM; k0 += 8) {
        float4 av = *reinterpret_cast<const float4*>(Ag + k0);
        float4 bv = *reinterpret_cast<const float4*>(Bg + k0);
        As[lc + 0][lr] = av.x; As[lc + 1][lr] = av.y;
        As[lc + 2][lr] = av.z; As[lc + 3][lr] = av.w;
        Bs[lc + 0][lr] = bv.x; Bs[lc + 1][lr] = bv.y;
        Bs[lc + 2][lr] = bv.z; Bs[lc + 3][lr] = bv.w;
        __syncthreads();
#pragma unroll
        for (int k = 0; k < 8; k++) {
            float ar[8], br[8];
            *reinterpret_cast<float4*>(&ar[0]) = *reinterpret_cast<const float4*>(&As[k][ty * 4]);
            *reinterpret_cast<float4*>(&ar[4]) = *reinterpret_cast<const float4*>(&As[k][64 + ty * 4]);
            *reinterpret_cast<float4*>(&br[0]) = *reinterpret_cast<const float4*>(&Bs[k][tx * 4]);
            *reinterpret_cast<float4*>(&br[4]) = *reinterpret_cast<const float4*>(&Bs[k][64 + tx * 4]);
#pragma unroll
            for (int i = 0; i < 8; i++)
#pragma unroll
                for (int j = 0; j < 8; j++) acc[i][j] = fmaf(ar[i], br[j], acc[i][j]);
        }
        __syncthreads();
    }
#pragma unroll
    for (int i = 0; i < 8; i++) {
        int m = bm + ((i < 4) ? (ty * 4 + i) : (64 + ty * 4 + i - 4));
        float* cp = g_C + (size_t)m * NCOLS + bn;
        *reinterpret_cast<float4*>(cp + tx * 4) =
            make_float4(acc[i][0], acc[i][1], acc[i][2], acc[i][3]);
        *reinterpret_cast<float4*>(cp + 64 + tx * 4) =
            make_float4(acc[i][4], acc[i][5], acc[i][6], acc[i][7]);
    }
}

// ---------------------------------------------------------------------------
// Kernel 3: add bias + L2-normalize each query row (warp per row)
// ---------------------------------------------------------------------------
__global__ void k_bias_norm(const float* __restrict__ bias) {
    int gw = (blockIdx.x * blockDim.x + threadIdx.x) >> 5;
    int lane = threadIdx.x & 31;
    if (gw >= MROWS * NSTEP) return;
    int m = gw / NSTEP, s = gw % NSTEP;
    float* row = g_C + (size_t)m * NCOLS + (size_t)s * DIM;
    const float4* b4 = reinterpret_cast<const float4*>(bias + (size_t)s * DIM);
    float4 v0 = reinterpret_cast<float4*>(row)[lane * 2];
    float4 v1 = reinterpret_cast<float4*>(row)[lane * 2 + 1];
    float4 c0 = b4[lane * 2];
    float4 c1 = b4[lane * 2 + 1];
    v0.x += c0.x; v0.y += c0.y; v0.z += c0.z; v0.w += c0.w;
    v1.x += c1.x; v1.y += c1.y; v1.z += c1.z; v1.w += c1.w;
    float ss = v0.x*v0.x + v0.y*v0.y + v0.z*v0.z + v0.w*v0.w
             + v1.x*v1.x + v1.y*v1.y + v1.z*v1.z + v1.w*v1.w;
    ss = wsum(ss);
    float inv = 1.0f / fmaxf(sqrtf(ss), 1e-12f);
    v0.x *= inv; v0.y *= inv; v0.z *= inv; v0.w *= inv;
    v1.x *= inv; v1.y *= inv; v1.z *= inv; v1.w *= inv;
    reinterpret_cast<float4*>(row)[lane * 2] = v0;
    reinterpret_cast<float4*>(row)[lane * 2 + 1] = v1;
}

// ---------------------------------------------------------------------------
// Kernel 4: per-(step,b,t) InfoNCE partial loss
//   Warp-per-item (13 items/warp); per-item dot = 4 chained bf16x2 FMAs
//   (query rounded to bf16 once per lane). Per-lane partials go to smem;
//   one 101-thread pass reduces them. All warp ops fully converged.
// ---------------------------------------------------------------------------
__global__ __launch_bounds__(256) void k_loss() {
    int s = blockIdx.y + 1;           // step 1..12
    int T2 = TLEN - s;
    int bt = blockIdx.x;              // 0..2047
    int b = bt >> 8, t = bt & 255;
    int tid = threadIdx.x;
    __shared__ float sp[101 * 33];    // per-lane partials, stride 33 (pad)
    __shared__ float logits[101];
    __shared__ int sidx[101];         // row * 32 (uint4 units, 512B rows)
    if (t >= T2) {
        if (tid == 0) g_part[(size_t)(s - 1) * MROWS + bt] = 0.0f;
        return;
    }
    uint32_t span = (uint32_t)(BATCH * T2);
    if (tid < 101) {
        int row;
        if (tid == 0) {
            row = b * TLEN + t + s;   // positive
        } else {
            uint32_t k0, k1;
            tf2x32(0u, 1234u, 0u, (uint32_t)s, k0, k1);   // fold_in(key(1234), s)
            uint32_t n = span * NNEG;
            uint32_t i = (uint32_t)((b * T2 + t) * NNEG + (tid - 1));
            uint32_t hi = tf_bits32(k0, k1, i);
            uint32_t lo = tf_bits32(k0, k1, n + i);
            uint32_t m16 = 65536u % span;
            uint32_t mult = (m16 * m16) % span;
            uint32_t off = ((hi % span) * mult + (lo % span)) % span;
            uint32_t b2 = off / (uint32_t)T2;
            uint32_t t2 = off - b2 * (uint32_t)T2;
            row = (int)(b2 * TLEN + (uint32_t)s + t2);
        }
        sidx[tid] = row * 32;
    }
    __syncthreads();

    int lane = tid & 31, w = tid >> 5;

    // Query: this lane's 8 contiguous f32 -> 4 bf16x2 words
    const float* qrow = g_C + (size_t)(b * TLEN + t) * NCOLS + (size_t)(s - 1) * DIM;
    const float4* q4 = reinterpret_cast<const float4*>(qrow);
    float4 qa = q4[lane * 2];
    float4 qb = q4[lane * 2 + 1];
    uint32_t qh0 = f2_to_bf2(qa.x, qa.y);
    uint32_t qh1 = f2_to_bf2(qa.z, qa.w);
    uint32_t qh2 = f2_to_bf2(qb.x, qb.y);
    uint32_t qh3 = f2_to_bf2(qb.z, qb.w);

    const uint4* tn4 = reinterpret_cast<const uint4*>(g_tn);
#pragma unroll 4
    for (int it = 0; it < 13; it++) {
        int g = it * 8 + w;           // item id; uniform across warp
        int gc = min(g, 100);
        uint4 v = __ldg(tn4 + sidx[gc] + lane);
        uint32_t acc = 0;
        bfma2(acc, v.x, qh0);
        bfma2(acc, v.y, qh1);
        bfma2(acc, v.z, qh2);
        bfma2(acc, v.w, qh3);
        // exact unpack of the bf16x2 accumulator halves
        float part = __uint_as_float(acc << 16)
                   + __uint_as_float(acc & 0xffff0000u);
        if (g < 101) sp[gc * 33 + lane] = part;   // warp-uniform predicate
    }
    __syncthreads();

    // Reduce 32 lane-partials per item (thread i -> item i; conflict-free
    // thanks to the stride-33 padding)
    if (tid < 101) {
        const float* r = sp + tid * 33;
        float s0 = 0.f, s1 = 0.f, s2 = 0.f, s3 = 0.f;
#pragma unroll
        for (int k = 0; k < 32; k += 4) {
            s0 += r[k]; s1 += r[k + 1]; s2 += r[k + 2]; s3 += r[k + 3];
        }
        logits[tid] = ((s0 + s1) + (s2 + s3)) * 10.0f;   // /TEMP
    }
    __syncthreads();

    if (w == 0) {
        float mx = -1e30f;
        for (int i = lane; i < 101; i += 32) mx = fmaxf(mx, logits[i]);
        mx = wmax(mx);
        float sum = 0.0f;
        for (int i = lane; i < 101; i += 32) sum += __expf(logits[i] - mx);
        sum = wsum(sum);
        if (lane == 0) {
            float lse = mx + __logf(sum);
            g_part[(size_t)(s - 1) * MROWS + bt] =
                (lse - logits[0]) / (float)(NSTEP * BATCH * T2);
        }
    }
}

// ---------------------------------------------------------------------------
// Kernel 5: deterministic final reduction
// ---------------------------------------------------------------------------
__global__ void k_reduce(float* __restrict__ out) {
    __shared__ float sm[256];
    int tid = threadIdx.x;
    float s = 0.0f;
    for (int i = tid; i < NSTEP * MROWS; i += 256) s += g_part[i];
    sm[tid] = s;
    __syncthreads();
    for (int o = 128; o; o >>= 1) {
        if (tid < o) sm[tid] += sm[tid + o];
        __syncthreads();
    }
    if (tid == 0) out[0] = sm[0];
}

// ---------------------------------------------------------------------------
extern "C" void kernel_launch(void* const* d_in, const int* in_sizes, int n_in,
                              void* d_out, int out_size) {
    const float* ctx  = (const float*)d_in[0];
    const float* tgt  = (const float*)d_in[1];
    const float* W    = (const float*)d_in[2];
    const float* bias = (const float*)d_in[3];
    float* out = (float*)d_out;

    k_norm_targets<<<(BATCH * TLEN) / 8, 256>>>(tgt);
    k_gemm<<<dim3(NCOLS / 128, MROWS / 128), 256>>>(ctx, W);
    k_bias_norm<<<(MROWS * NSTEP) / 8, 256>>>(bias);
    k_loss<<<dim3(MROWS, NSTEP), 256>>>();
    k_reduce<<<1, 256>>>(out);
}